// round 11
// baseline (speedup 1.0000x reference)
#include <cuda_runtime.h>
#include <math.h>
#include <stdint.h>

#define BB 32
#define GG 64
#define NN 4096
#define CC 384
#define NSEG 8
#define SCALE 0.051031036307982884f  /* 384^-0.5 */

// ---------------- scratch (device globals; no allocation allowed) ----------------
__device__ float g_qa[BB*GG*CC];     // query @ q_w.T + q_b
__device__ float g_q2[BB*GG*CC];     // qa @ k_w
__device__ float g_Mm[CC*CC];        // p_w @ v_w
__device__ float g_pvb[CC];          // p_w @ v_b
__device__ float g_t[BB*GG];         // qa . k_b  per (b,g)
__device__ int   g_idx[BB*NN];       // argmax group per (b,n)
__device__ int   g_cnt[BB*GG];       // counts per (b,g)
__device__ float g_Sp[(size_t)NSEG*BB*GG*CC]; // n-segment partial key sums

// ---------------- f32x2 packed helpers (sm_103a) ----------------
__device__ __forceinline__ void fma_f32x2(unsigned long long& d, unsigned long long a,
                                          unsigned long long b, unsigned long long c) {
    asm("fma.rn.f32x2 %0, %1, %2, %3;" : "=l"(d) : "l"(a), "l"(b), "l"(c));
}
__device__ __forceinline__ unsigned long long pack2(float lo, float hi) {
    unsigned long long d;
    asm("mov.b64 %0, {%1, %2};" : "=l"(d) : "f"(lo), "f"(hi));
    return d;
}
__device__ __forceinline__ void unpack2(float& lo, float& hi, unsigned long long v) {
    asm("mov.b64 {%0, %1}, %2;" : "=f"(lo), "=f"(hi) : "l"(v));
}

// ---------------- tf32 helpers (mma.sync path; baseline sm_80+ PTX) ----------------
// mask split: hi keeps 10 mantissa bits (valid tf32); lo = x - hi exact.
__device__ __forceinline__ float maskhi(float x) {
    return __uint_as_float(__float_as_uint(x) & 0xFFFFE000u);
}
#define MMA_TF32(d, a, b)                                                       \
    asm volatile("mma.sync.aligned.m16n8k8.row.col.f32.tf32.tf32.f32 "          \
        "{%0,%1,%2,%3}, {%4,%5,%6,%7}, {%8,%9}, {%0,%1,%2,%3};"                 \
        : "+f"((d)[0]), "+f"((d)[1]), "+f"((d)[2]), "+f"((d)[3])                \
        : "r"((a)[0]), "r"((a)[1]), "r"((a)[2]), "r"((a)[3]),                   \
          "r"((b)[0]), "r"((b)[1]))

// ---------------- zero counts ----------------
__global__ void k_zero(int* cnt) {
    int t = blockIdx.x * blockDim.x + threadIdx.x;
    if (t < BB*GG) cnt[t] = 0;
}

// ---------------- generic 64x64-tile fp32 GEMM (f32x2 inner) ----------------
// AM: 0 = A row-major; 2 = row-major sum of NSEG partials
// BM: 0 = B k-major B[k*C+j]; 1 = B n-major B[j*C+k]
// EPI:0 = store; 1 = +bias[j]; 2 = out epilogue ((v+cnt*pvb)/(cnt+1)+bias);
//     3 = plain store + aux[i] = A[i,:].bias (dot-vector epilogue, blockIdx.x==0 writes)
template<int AM, int BM, int EPI>
__global__ void __launch_bounds__(256) k_gemm64(const float* __restrict__ A,
                                                const float* __restrict__ Bm,
                                                float* __restrict__ Cc,
                                                const float* __restrict__ bias,
                                                const int* __restrict__ cnt,
                                                const float* __restrict__ pvb,
                                                float* __restrict__ aux) {
    __shared__ __align__(16) float As[16][68];
    __shared__ __align__(16) float Bs[16][68];
    int j0 = blockIdx.x * 64, i0 = blockIdx.y * 64;
    int tid = threadIdx.x;
    unsigned long long acc2[4][2];
    #pragma unroll
    for (int i = 0; i < 4; i++) { acc2[i][0] = 0ULL; acc2[i][1] = 0ULL; }
    float tacc = 0.f;
    for (int k0 = 0; k0 < CC; k0 += 16) {
        {
            int r = tid >> 2, kq = (tid & 3) * 4;
            float4 v;
            if (AM == 2) {
                const float* p = &A[(size_t)(i0 + r) * CC + k0 + kq];
                const size_t PS = (size_t)BB * GG * CC;
                float4 s = *(const float4*)p;
                #pragma unroll
                for (int q = 1; q < NSEG; q++) {
                    float4 vq = *(const float4*)(p + (size_t)q * PS);
                    s.x += vq.x; s.y += vq.y; s.z += vq.z; s.w += vq.w;
                }
                v = s;
            } else {
                v = *(const float4*)&A[(size_t)(i0 + r) * CC + k0 + kq];
            }
            As[kq + 0][r] = v.x; As[kq + 1][r] = v.y;
            As[kq + 2][r] = v.z; As[kq + 3][r] = v.w;
        }
        if (BM == 0) {
            int kk = tid >> 4, j4 = (tid & 15) * 4;
            *(float4*)&Bs[kk][j4] = *(const float4*)&Bm[(size_t)(k0 + kk) * CC + j0 + j4];
        } else {
            int jr = tid >> 2, kq = (tid & 3) * 4;
            float4 v = *(const float4*)&Bm[(size_t)(jr + j0) * CC + k0 + kq];
            Bs[kq + 0][jr] = v.x; Bs[kq + 1][jr] = v.y;
            Bs[kq + 2][jr] = v.z; Bs[kq + 3][jr] = v.w;
        }
        __syncthreads();
        if (EPI == 3) {
            if (tid < 64) {
                #pragma unroll
                for (int kk = 0; kk < 16; kk++)
                    tacc += As[kk][tid] * bias[k0 + kk];
            }
        }
        int ty = tid >> 4, tx = tid & 15;
        #pragma unroll
        for (int kk = 0; kk < 16; kk++) {
            float4 a4 = *(const float4*)&As[kk][ty * 4];
            ulonglong2 bb = *(const ulonglong2*)&Bs[kk][tx * 4];
            unsigned long long av[4] = {pack2(a4.x, a4.x), pack2(a4.y, a4.y),
                                        pack2(a4.z, a4.z), pack2(a4.w, a4.w)};
            #pragma unroll
            for (int i = 0; i < 4; i++) {
                fma_f32x2(acc2[i][0], av[i], bb.x, acc2[i][0]);
                fma_f32x2(acc2[i][1], av[i], bb.y, acc2[i][1]);
            }
        }
        __syncthreads();
    }
    int ty = tid >> 4, tx = tid & 15;
    #pragma unroll
    for (int i = 0; i < 4; i++) {
        int r = i0 + ty * 4 + i;
        float a0, a1, a2, a3;
        unpack2(a0, a1, acc2[i][0]);
        unpack2(a2, a3, acc2[i][1]);
        float accv[4] = {a0, a1, a2, a3};
        #pragma unroll
        for (int j = 0; j < 4; j++) {
            int c = j0 + tx * 4 + j;
            float v = accv[j];
            if (EPI == 1) v += bias[c];
            if (EPI == 2) {
                float cf = (float)cnt[r];
                v = (v + cf * pvb[c]) / (cf + 1.0f) + bias[c];
            }
            Cc[(size_t)r * CC + c] = v;
        }
    }
    if (EPI == 3) {
        if (blockIdx.x == 0 && tid < 64) aux[i0 + tid] = tacc;
    }
}

// ===== fused logits (tf32x3 mma.sync) + shuffle softmax(over G) + argmax + counts =====
// Block: one b, 128-n tile, all 64 g. 128 threads = 4 warps.
// smem = 26.9KB -> 8 blocks/SM. Epilogue uses shfl_xor butterflies across the 8 lanes
// (same kr, varying gr) that own each column's 64 g values; no smem staging.
__global__ void __launch_bounds__(128, 8) k_attn(const float* __restrict__ key,
                                                 float* __restrict__ soft,
                                                 int* __restrict__ idxp,
                                                 int* __restrict__ cntp) {
    __shared__ __align__(16) float sAh[16][72];
    __shared__ __align__(16) float sAl[16][72];
    __shared__ __align__(16) float sBh[16][136];
    __shared__ __align__(16) float sBl[16][136];
    __shared__ float tsm[GG];

    int b = blockIdx.y;
    int n_base = blockIdx.x * 128;
    int tid = threadIdx.x, lane = tid & 31, warp = tid >> 5;
    if (tid < GG) tsm[tid] = g_t[b * GG + tid];

    const float* q2 = g_q2 + (size_t)b * GG * CC;
    const float* kp = key + ((size_t)b * NN + n_base) * CC;

    float acc[4][4][4];
    #pragma unroll
    for (int mt = 0; mt < 4; mt++)
        #pragma unroll
        for (int nt = 0; nt < 4; nt++)
            #pragma unroll
            for (int r = 0; r < 4; r++) acc[mt][nt][r] = 0.f;

    int kr = lane & 3, gr = lane >> 2;
    int wb = warp * 32;

    for (int k0 = 0; k0 < CC; k0 += 16) {
        {   // A (q2): 64g x 16k, mask split hi/lo (separate arrays: conflict-free)
            int g = tid >> 1, ks = (tid & 1) * 8;
            float4 v0 = *(const float4*)&q2[(size_t)g * CC + k0 + ks];
            float4 v1 = *(const float4*)&q2[(size_t)g * CC + k0 + ks + 4];
            float f[8] = {v0.x, v0.y, v0.z, v0.w, v1.x, v1.y, v1.z, v1.w};
            #pragma unroll
            for (int i = 0; i < 8; i++) {
                float h = maskhi(f[i]);
                sAh[ks + i][g] = h;
                sAl[ks + i][g] = f[i] - h;
            }
        }
        #pragma unroll
        for (int p = 0; p < 4; p++) {  // B (key): 128n x 16k, mask split hi/lo
            int nn = (tid >> 2) + p * 32, kq = (tid & 3) * 4;
            float4 v = *(const float4*)&kp[(size_t)nn * CC + k0 + kq];
            float f[4] = {v.x, v.y, v.z, v.w};
            #pragma unroll
            for (int i = 0; i < 4; i++) {
                float h = maskhi(f[i]);
                sBh[kq + i][nn] = h;
                sBl[kq + i][nn] = f[i] - h;
            }
        }
        __syncthreads();
        #pragma unroll
        for (int s = 0; s < 2; s++) {
            int k1 = s * 8 + kr, k2 = k1 + 4;
            uint32_t bh[4][2], bl[4][2];
            #pragma unroll
            for (int nt = 0; nt < 4; nt++) {
                int nc = wb + nt * 8 + gr;
                bh[nt][0] = __float_as_uint(sBh[k1][nc]);
                bh[nt][1] = __float_as_uint(sBh[k2][nc]);
                bl[nt][0] = __float_as_uint(sBl[k1][nc]);
                bl[nt][1] = __float_as_uint(sBl[k2][nc]);
            }
            #pragma unroll
            for (int mt = 0; mt < 4; mt++) {
                int g0 = mt * 16 + gr;
                uint32_t ah[4], al[4];
                ah[0] = __float_as_uint(sAh[k1][g0]);
                ah[1] = __float_as_uint(sAh[k1][g0 + 8]);
                ah[2] = __float_as_uint(sAh[k2][g0]);
                ah[3] = __float_as_uint(sAh[k2][g0 + 8]);
                al[0] = __float_as_uint(sAl[k1][g0]);
                al[1] = __float_as_uint(sAl[k1][g0 + 8]);
                al[2] = __float_as_uint(sAl[k2][g0]);
                al[3] = __float_as_uint(sAl[k2][g0 + 8]);
                #pragma unroll
                for (int nt = 0; nt < 4; nt++) {
                    MMA_TF32(acc[mt][nt], ah, bh[nt]);
                    MMA_TF32(acc[mt][nt], ah, bl[nt]);
                    MMA_TF32(acc[mt][nt], al, bh[nt]);
                }
            }
        }
        __syncthreads();
    }

    // ---- shuffle-based softmax/argmax epilogue (no smem staging) ----
    float tv0[4], tv1[4];
    #pragma unroll
    for (int mt = 0; mt < 4; mt++) { tv0[mt] = tsm[16 * mt + gr]; tv1[mt] = tsm[16 * mt + 8 + gr]; }

    float* softb = soft + (size_t)b * GG * NN;
    #pragma unroll
    for (int nt = 0; nt < 4; nt++) {
        float e[2][8]; int am[2]; float inv[2];
        #pragma unroll
        for (int p = 0; p < 2; p++) {
            float l[8];
            #pragma unroll
            for (int mt = 0; mt < 4; mt++) {
                l[2 * mt]     = SCALE * (acc[mt][nt][p]     + tv0[mt]);
                l[2 * mt + 1] = SCALE * (acc[mt][nt][2 + p] + tv1[mt]);
            }
            // local first-max (ascending g: i -> g = 16*(i/2) + 8*(i&1) + gr)
            float m = l[0]; int a = gr;
            #pragma unroll
            for (int i = 1; i < 8; i++) {
                int gi = 16 * (i >> 1) + 8 * (i & 1) + gr;
                if (l[i] > m) { m = l[i]; a = gi; }
            }
            // cross-lane reduce over gr (lanes xor 4,8,16); tie -> lowest g
            #pragma unroll
            for (int o = 4; o <= 16; o <<= 1) {
                float mo = __shfl_xor_sync(0xFFFFFFFFu, m, o);
                int   ao = __shfl_xor_sync(0xFFFFFFFFu, a, o);
                if (mo > m || (mo == m && ao < a)) { m = mo; a = ao; }
            }
            float s = 0.f;
            #pragma unroll
            for (int i = 0; i < 8; i++) { e[p][i] = __expf(l[i] - m); s += e[p][i]; }
            #pragma unroll
            for (int o = 4; o <= 16; o <<= 1) s += __shfl_xor_sync(0xFFFFFFFFu, s, o);
            inv[p] = 1.0f / s; am[p] = a;
        }
        int cb = n_base + wb + nt * 8 + 2 * kr;
        #pragma unroll
        for (int mt = 0; mt < 4; mt++) {
            int g0 = 16 * mt + gr, g1 = g0 + 8;
            *(float2*)&softb[(size_t)g0 * NN + cb] =
                make_float2(e[0][2 * mt] * inv[0], e[1][2 * mt] * inv[1]);
            *(float2*)&softb[(size_t)g1 * NN + cb] =
                make_float2(e[0][2 * mt + 1] * inv[0], e[1][2 * mt + 1] * inv[1]);
        }
        if (gr == 0) {
            idxp[b * NN + cb]     = am[0];
            idxp[b * NN + cb + 1] = am[1];
            atomicAdd(&cntp[b * GG + am[0]], 1);
            atomicAdd(&cntp[b * GG + am[1]], 1);
        }
    }
}

// ---------------- segment sums of key rows by argmax group ----------------
__global__ void __launch_bounds__(128) k_seg(const float* __restrict__ key) {
    __shared__ float S[GG][128];
    __shared__ int sidx[512];
    int ns = blockIdx.x, cb = blockIdx.y, b = blockIdx.z;
    int tid = threadIdx.x;
    int c0 = cb * 128, nb = ns * 512;
    for (int i = tid; i < GG * 128; i += 128) ((float*)S)[i] = 0.f;
    for (int i = tid; i < 512; i += 128) sidx[i] = g_idx[b * NN + nb + i];
    __syncthreads();
    const float* kp = key + ((size_t)(b * NN + nb)) * CC + c0;
    for (int n = 0; n < 512; n += 8) {
        float x[8];
        #pragma unroll
        for (int i = 0; i < 8; i++) x[i] = kp[(size_t)(n + i) * CC + tid];
        #pragma unroll
        for (int i = 0; i < 8; i++) S[sidx[n + i]][tid] += x[i];
    }
    __syncthreads();
    float* dst = g_Sp + (size_t)ns * BB * GG * CC + (size_t)b * GG * CC + c0 + tid;
    for (int g = 0; g < GG; g++) dst[(size_t)g * CC] = S[g][tid];
}

// ---------------- launcher ----------------
extern "C" void kernel_launch(void* const* d_in, const int* in_sizes, int n_in,
                              void* d_out, int out_size) {
    const float* query = (const float*)d_in[0];
    const float* key   = (const float*)d_in[1];
    const float* q_w   = (const float*)d_in[2];
    const float* q_b   = (const float*)d_in[3];
    const float* k_w   = (const float*)d_in[4];
    const float* k_b   = (const float*)d_in[5];
    const float* v_w   = (const float*)d_in[6];
    const float* v_b   = (const float*)d_in[7];
    const float* p_w   = (const float*)d_in[8];
    const float* p_b   = (const float*)d_in[9];
    (void)n_in; (void)in_sizes;

    float* out  = (float*)d_out;
    float* soft = out + ((size_t)out_size - (size_t)BB * GG * NN);

    float *pqa, *pq2, *pMm, *ppvb, *pSp, *pt;
    int *pidx, *pcnt;
    cudaGetSymbolAddress((void**)&pqa,  g_qa);
    cudaGetSymbolAddress((void**)&pq2,  g_q2);
    cudaGetSymbolAddress((void**)&pMm,  g_Mm);
    cudaGetSymbolAddress((void**)&ppvb, g_pvb);
    cudaGetSymbolAddress((void**)&pSp,  g_Sp);
    cudaGetSymbolAddress((void**)&pt,   g_t);
    cudaGetSymbolAddress((void**)&pidx, g_idx);
    cudaGetSymbolAddress((void**)&pcnt, g_cnt);

    // 1. qa = query @ q_w.T + q_b
    k_gemm64<0, 1, 1><<<dim3(6, 32), 256>>>(query, q_w, pqa, q_b, nullptr, nullptr, nullptr);
    // 2. q2 = qa @ k_w ; t = qa . k_b (epilogue)
    k_gemm64<0, 0, 3><<<dim3(6, 32), 256>>>(pqa, k_w, pq2, k_b, nullptr, nullptr, pt);
    // 3. zero counts (independent; placed here so k_attn is capture slot #4)
    k_zero<<<2, 1024>>>(pcnt);
    // 4. fused logits(tf32x3 mma) + shuffle softmax + argmax + counts
    k_attn<<<dim3(NN / 128, BB), 128>>>(key, soft, pidx, pcnt);
    // 5. Mm = p_w @ v_w ; pvb = p_w . v_b (epilogue)
    k_gemm64<0, 0, 3><<<dim3(6, 6), 256>>>(p_w, v_w, pMm, v_b, nullptr, nullptr, ppvb);
    // 6. segment sums of key
    k_seg<<<dim3(NSEG, 3, BB), 128>>>(key);
    // 7. out = (S @ Mm.T + cnt*pvb)/(cnt+1) + p_b
    k_gemm64<2, 1, 2><<<dim3(6, 32), 256>>>(pSp, pMm, out, p_b, pcnt, ppvb, nullptr);
}

// round 12
// speedup vs baseline: 1.0000x; 1.0000x over previous
#include <cuda_runtime.h>
#include <math.h>
#include <stdint.h>

#define BB 32
#define GG 64
#define NN 4096
#define CC 384
#define NSEG 8
#define SCALE 0.051031036307982884f  /* 384^-0.5 */

// ---------------- scratch (device globals; no allocation allowed) ----------------
__device__ float g_qa[BB*GG*CC];     // query @ q_w.T + q_b
__device__ float g_q2[BB*GG*CC];     // qa @ k_w
__device__ float g_Mm[CC*CC];        // p_w @ v_w
__device__ float g_pvb[CC];          // p_w @ v_b
__device__ float g_t[BB*GG];         // qa . k_b  per (b,g)
__device__ int   g_idx[BB*NN];       // argmax group per (b,n)
__device__ int   g_cnt[BB*GG];       // counts per (b,g)
__device__ float g_Sp[(size_t)NSEG*BB*GG*CC]; // n-segment partial key sums

// ---------------- f32x2 packed helpers (sm_103a) ----------------
__device__ __forceinline__ void fma_f32x2(unsigned long long& d, unsigned long long a,
                                          unsigned long long b, unsigned long long c) {
    asm("fma.rn.f32x2 %0, %1, %2, %3;" : "=l"(d) : "l"(a), "l"(b), "l"(c));
}
__device__ __forceinline__ unsigned long long pack2(float lo, float hi) {
    unsigned long long d;
    asm("mov.b64 %0, {%1, %2};" : "=l"(d) : "f"(lo), "f"(hi));
    return d;
}
__device__ __forceinline__ void unpack2(float& lo, float& hi, unsigned long long v) {
    asm("mov.b64 {%0, %1}, %2;" : "=f"(lo), "=f"(hi) : "l"(v));
}

// ---------------- tf32 helpers (mma.sync path; baseline sm_80+ PTX) ----------------
// mask split: hi keeps 10 mantissa bits (valid tf32); lo = x - hi exact.
__device__ __forceinline__ float maskhi(float x) {
    return __uint_as_float(__float_as_uint(x) & 0xFFFFE000u);
}
#define MMA_TF32(d, a, b)                                                       \
    asm volatile("mma.sync.aligned.m16n8k8.row.col.f32.tf32.tf32.f32 "          \
        "{%0,%1,%2,%3}, {%4,%5,%6,%7}, {%8,%9}, {%0,%1,%2,%3};"                 \
        : "+f"((d)[0]), "+f"((d)[1]), "+f"((d)[2]), "+f"((d)[3])                \
        : "r"((a)[0]), "r"((a)[1]), "r"((a)[2]), "r"((a)[3]),                   \
          "r"((b)[0]), "r"((b)[1]))

// ---------------- zero counts ----------------
__global__ void k_zero(int* cnt) {
    int t = blockIdx.x * blockDim.x + threadIdx.x;
    if (t < BB*GG) cnt[t] = 0;
}

// ---------------- generic 64x64-tile fp32 GEMM (f32x2 inner) ----------------
// AM: 0 = A row-major; 2 = row-major sum of NSEG partials
// BM: 0 = B k-major B[k*C+j]; 1 = B n-major B[j*C+k]
// EPI:0 = store; 1 = +bias[j]; 2 = out epilogue ((v+cnt*pvb)/(cnt+1)+bias);
//     3 = plain store + aux[i] = A[i,:].bias (dot-vector epilogue, blockIdx.x==0 writes)
template<int AM, int BM, int EPI>
__global__ void __launch_bounds__(256) k_gemm64(const float* __restrict__ A,
                                                const float* __restrict__ Bm,
                                                float* __restrict__ Cc,
                                                const float* __restrict__ bias,
                                                const int* __restrict__ cnt,
                                                const float* __restrict__ pvb,
                                                float* __restrict__ aux) {
    __shared__ __align__(16) float As[16][68];
    __shared__ __align__(16) float Bs[16][68];
    int j0 = blockIdx.x * 64, i0 = blockIdx.y * 64;
    int tid = threadIdx.x;
    unsigned long long acc2[4][2];
    #pragma unroll
    for (int i = 0; i < 4; i++) { acc2[i][0] = 0ULL; acc2[i][1] = 0ULL; }
    float tacc = 0.f;
    for (int k0 = 0; k0 < CC; k0 += 16) {
        {
            int r = tid >> 2, kq = (tid & 3) * 4;
            float4 v;
            if (AM == 2) {
                const float* p = &A[(size_t)(i0 + r) * CC + k0 + kq];
                const size_t PS = (size_t)BB * GG * CC;
                float4 s = *(const float4*)p;
                #pragma unroll
                for (int q = 1; q < NSEG; q++) {
                    float4 vq = *(const float4*)(p + (size_t)q * PS);
                    s.x += vq.x; s.y += vq.y; s.z += vq.z; s.w += vq.w;
                }
                v = s;
            } else {
                v = *(const float4*)&A[(size_t)(i0 + r) * CC + k0 + kq];
            }
            As[kq + 0][r] = v.x; As[kq + 1][r] = v.y;
            As[kq + 2][r] = v.z; As[kq + 3][r] = v.w;
        }
        if (BM == 0) {
            int kk = tid >> 4, j4 = (tid & 15) * 4;
            *(float4*)&Bs[kk][j4] = *(const float4*)&Bm[(size_t)(k0 + kk) * CC + j0 + j4];
        } else {
            int jr = tid >> 2, kq = (tid & 3) * 4;
            float4 v = *(const float4*)&Bm[(size_t)(jr + j0) * CC + k0 + kq];
            Bs[kq + 0][jr] = v.x; Bs[kq + 1][jr] = v.y;
            Bs[kq + 2][jr] = v.z; Bs[kq + 3][jr] = v.w;
        }
        __syncthreads();
        if (EPI == 3) {
            if (tid < 64) {
                #pragma unroll
                for (int kk = 0; kk < 16; kk++)
                    tacc += As[kk][tid] * bias[k0 + kk];
            }
        }
        int ty = tid >> 4, tx = tid & 15;
        #pragma unroll
        for (int kk = 0; kk < 16; kk++) {
            float4 a4 = *(const float4*)&As[kk][ty * 4];
            ulonglong2 bb = *(const ulonglong2*)&Bs[kk][tx * 4];
            unsigned long long av[4] = {pack2(a4.x, a4.x), pack2(a4.y, a4.y),
                                        pack2(a4.z, a4.z), pack2(a4.w, a4.w)};
            #pragma unroll
            for (int i = 0; i < 4; i++) {
                fma_f32x2(acc2[i][0], av[i], bb.x, acc2[i][0]);
                fma_f32x2(acc2[i][1], av[i], bb.y, acc2[i][1]);
            }
        }
        __syncthreads();
    }
    int ty = tid >> 4, tx = tid & 15;
    #pragma unroll
    for (int i = 0; i < 4; i++) {
        int r = i0 + ty * 4 + i;
        float a0, a1, a2, a3;
        unpack2(a0, a1, acc2[i][0]);
        unpack2(a2, a3, acc2[i][1]);
        float accv[4] = {a0, a1, a2, a3};
        #pragma unroll
        for (int j = 0; j < 4; j++) {
            int c = j0 + tx * 4 + j;
            float v = accv[j];
            if (EPI == 1) v += bias[c];
            if (EPI == 2) {
                float cf = (float)cnt[r];
                v = (v + cf * pvb[c]) / (cf + 1.0f) + bias[c];
            }
            Cc[(size_t)r * CC + c] = v;
        }
    }
    if (EPI == 3) {
        if (blockIdx.x == 0 && tid < 64) aux[i0 + tid] = tacc;
    }
}

// ===== fused logits (tf32x3 mma.sync) + shuffle softmax(over G) + argmax + counts =====
// Block: one b, 128-n tile, all 64 g. 128 threads = 4 warps.
// smem = 26.9KB -> 8 blocks/SM. Epilogue uses shfl_xor butterflies across the 8 lanes
// (same kr, varying gr) that own each column's 64 g values; no smem staging.
__global__ void __launch_bounds__(128, 8) k_attn(const float* __restrict__ key,
                                                 float* __restrict__ soft,
                                                 int* __restrict__ idxp,
                                                 int* __restrict__ cntp) {
    __shared__ __align__(16) float sAh[16][72];
    __shared__ __align__(16) float sAl[16][72];
    __shared__ __align__(16) float sBh[16][136];
    __shared__ __align__(16) float sBl[16][136];
    __shared__ float tsm[GG];

    int b = blockIdx.y;
    int n_base = blockIdx.x * 128;
    int tid = threadIdx.x, lane = tid & 31, warp = tid >> 5;
    if (tid < GG) tsm[tid] = g_t[b * GG + tid];

    const float* q2 = g_q2 + (size_t)b * GG * CC;
    const float* kp = key + ((size_t)b * NN + n_base) * CC;

    float acc[4][4][4];
    #pragma unroll
    for (int mt = 0; mt < 4; mt++)
        #pragma unroll
        for (int nt = 0; nt < 4; nt++)
            #pragma unroll
            for (int r = 0; r < 4; r++) acc[mt][nt][r] = 0.f;

    int kr = lane & 3, gr = lane >> 2;
    int wb = warp * 32;

    for (int k0 = 0; k0 < CC; k0 += 16) {
        {   // A (q2): 64g x 16k, mask split hi/lo (separate arrays: conflict-free)
            int g = tid >> 1, ks = (tid & 1) * 8;
            float4 v0 = *(const float4*)&q2[(size_t)g * CC + k0 + ks];
            float4 v1 = *(const float4*)&q2[(size_t)g * CC + k0 + ks + 4];
            float f[8] = {v0.x, v0.y, v0.z, v0.w, v1.x, v1.y, v1.z, v1.w};
            #pragma unroll
            for (int i = 0; i < 8; i++) {
                float h = maskhi(f[i]);
                sAh[ks + i][g] = h;
                sAl[ks + i][g] = f[i] - h;
            }
        }
        #pragma unroll
        for (int p = 0; p < 4; p++) {  // B (key): 128n x 16k, mask split hi/lo
            int nn = (tid >> 2) + p * 32, kq = (tid & 3) * 4;
            float4 v = *(const float4*)&kp[(size_t)nn * CC + k0 + kq];
            float f[4] = {v.x, v.y, v.z, v.w};
            #pragma unroll
            for (int i = 0; i < 4; i++) {
                float h = maskhi(f[i]);
                sBh[kq + i][nn] = h;
                sBl[kq + i][nn] = f[i] - h;
            }
        }
        __syncthreads();
        #pragma unroll
        for (int s = 0; s < 2; s++) {
            int k1 = s * 8 + kr, k2 = k1 + 4;
            uint32_t bh[4][2], bl[4][2];
            #pragma unroll
            for (int nt = 0; nt < 4; nt++) {
                int nc = wb + nt * 8 + gr;
                bh[nt][0] = __float_as_uint(sBh[k1][nc]);
                bh[nt][1] = __float_as_uint(sBh[k2][nc]);
                bl[nt][0] = __float_as_uint(sBl[k1][nc]);
                bl[nt][1] = __float_as_uint(sBl[k2][nc]);
            }
            #pragma unroll
            for (int mt = 0; mt < 4; mt++) {
                int g0 = mt * 16 + gr;
                uint32_t ah[4], al[4];
                ah[0] = __float_as_uint(sAh[k1][g0]);
                ah[1] = __float_as_uint(sAh[k1][g0 + 8]);
                ah[2] = __float_as_uint(sAh[k2][g0]);
                ah[3] = __float_as_uint(sAh[k2][g0 + 8]);
                al[0] = __float_as_uint(sAl[k1][g0]);
                al[1] = __float_as_uint(sAl[k1][g0 + 8]);
                al[2] = __float_as_uint(sAl[k2][g0]);
                al[3] = __float_as_uint(sAl[k2][g0 + 8]);
                #pragma unroll
                for (int nt = 0; nt < 4; nt++) {
                    MMA_TF32(acc[mt][nt], ah, bh[nt]);
                    MMA_TF32(acc[mt][nt], ah, bl[nt]);
                    MMA_TF32(acc[mt][nt], al, bh[nt]);
                }
            }
        }
        __syncthreads();
    }

    // ---- shuffle-based softmax/argmax epilogue (no smem staging) ----
    float tv0[4], tv1[4];
    #pragma unroll
    for (int mt = 0; mt < 4; mt++) { tv0[mt] = tsm[16 * mt + gr]; tv1[mt] = tsm[16 * mt + 8 + gr]; }

    float* softb = soft + (size_t)b * GG * NN;
    #pragma unroll
    for (int nt = 0; nt < 4; nt++) {
        float e[2][8]; int am[2]; float inv[2];
        #pragma unroll
        for (int p = 0; p < 2; p++) {
            float l[8];
            #pragma unroll
            for (int mt = 0; mt < 4; mt++) {
                l[2 * mt]     = SCALE * (acc[mt][nt][p]     + tv0[mt]);
                l[2 * mt + 1] = SCALE * (acc[mt][nt][2 + p] + tv1[mt]);
            }
            // local first-max (ascending g: i -> g = 16*(i/2) + 8*(i&1) + gr)
            float m = l[0]; int a = gr;
            #pragma unroll
            for (int i = 1; i < 8; i++) {
                int gi = 16 * (i >> 1) + 8 * (i & 1) + gr;
                if (l[i] > m) { m = l[i]; a = gi; }
            }
            // cross-lane reduce over gr (lanes xor 4,8,16); tie -> lowest g
            #pragma unroll
            for (int o = 4; o <= 16; o <<= 1) {
                float mo = __shfl_xor_sync(0xFFFFFFFFu, m, o);
                int   ao = __shfl_xor_sync(0xFFFFFFFFu, a, o);
                if (mo > m || (mo == m && ao < a)) { m = mo; a = ao; }
            }
            float s = 0.f;
            #pragma unroll
            for (int i = 0; i < 8; i++) { e[p][i] = __expf(l[i] - m); s += e[p][i]; }
            #pragma unroll
            for (int o = 4; o <= 16; o <<= 1) s += __shfl_xor_sync(0xFFFFFFFFu, s, o);
            inv[p] = 1.0f / s; am[p] = a;
        }
        int cb = n_base + wb + nt * 8 + 2 * kr;
        #pragma unroll
        for (int mt = 0; mt < 4; mt++) {
            int g0 = 16 * mt + gr, g1 = g0 + 8;
            *(float2*)&softb[(size_t)g0 * NN + cb] =
                make_float2(e[0][2 * mt] * inv[0], e[1][2 * mt] * inv[1]);
            *(float2*)&softb[(size_t)g1 * NN + cb] =
                make_float2(e[0][2 * mt + 1] * inv[0], e[1][2 * mt + 1] * inv[1]);
        }
        if (gr == 0) {
            idxp[b * NN + cb]     = am[0];
            idxp[b * NN + cb + 1] = am[1];
            atomicAdd(&cntp[b * GG + am[0]], 1);
            atomicAdd(&cntp[b * GG + am[1]], 1);
        }
    }
}

// ---------------- segment sums of key rows by argmax group ----------------
__global__ void __launch_bounds__(128) k_seg(const float* __restrict__ key) {
    __shared__ float S[GG][128];
    __shared__ int sidx[512];
    int ns = blockIdx.x, cb = blockIdx.y, b = blockIdx.z;
    int tid = threadIdx.x;
    int c0 = cb * 128, nb = ns * 512;
    for (int i = tid; i < GG * 128; i += 128) ((float*)S)[i] = 0.f;
    for (int i = tid; i < 512; i += 128) sidx[i] = g_idx[b * NN + nb + i];
    __syncthreads();
    const float* kp = key + ((size_t)(b * NN + nb)) * CC + c0;
    for (int n = 0; n < 512; n += 8) {
        float x[8];
        #pragma unroll
        for (int i = 0; i < 8; i++) x[i] = kp[(size_t)(n + i) * CC + tid];
        #pragma unroll
        for (int i = 0; i < 8; i++) S[sidx[n + i]][tid] += x[i];
    }
    __syncthreads();
    float* dst = g_Sp + (size_t)ns * BB * GG * CC + (size_t)b * GG * CC + c0 + tid;
    for (int g = 0; g < GG; g++) dst[(size_t)g * CC] = S[g][tid];
}

// ---------------- launcher ----------------
extern "C" void kernel_launch(void* const* d_in, const int* in_sizes, int n_in,
                              void* d_out, int out_size) {
    const float* query = (const float*)d_in[0];
    const float* key   = (const float*)d_in[1];
    const float* q_w   = (const float*)d_in[2];
    const float* q_b   = (const float*)d_in[3];
    const float* k_w   = (const float*)d_in[4];
    const float* k_b   = (const float*)d_in[5];
    const float* v_w   = (const float*)d_in[6];
    const float* v_b   = (const float*)d_in[7];
    const float* p_w   = (const float*)d_in[8];
    const float* p_b   = (const float*)d_in[9];
    (void)n_in; (void)in_sizes;

    float* out  = (float*)d_out;
    float* soft = out + ((size_t)out_size - (size_t)BB * GG * NN);

    float *pqa, *pq2, *pMm, *ppvb, *pSp, *pt;
    int *pidx, *pcnt;
    cudaGetSymbolAddress((void**)&pqa,  g_qa);
    cudaGetSymbolAddress((void**)&pq2,  g_q2);
    cudaGetSymbolAddress((void**)&pMm,  g_Mm);
    cudaGetSymbolAddress((void**)&ppvb, g_pvb);
    cudaGetSymbolAddress((void**)&pSp,  g_Sp);
    cudaGetSymbolAddress((void**)&pt,   g_t);
    cudaGetSymbolAddress((void**)&pidx, g_idx);
    cudaGetSymbolAddress((void**)&pcnt, g_cnt);

    // 1. qa = query @ q_w.T + q_b
    k_gemm64<0, 1, 1><<<dim3(6, 32), 256>>>(query, q_w, pqa, q_b, nullptr, nullptr, nullptr);
    // 2. q2 = qa @ k_w ; t = qa . k_b (epilogue)
    k_gemm64<0, 0, 3><<<dim3(6, 32), 256>>>(pqa, k_w, pq2, k_b, nullptr, nullptr, pt);
    // 3. zero counts (independent; placed here so k_attn is capture slot #4)
    k_zero<<<2, 1024>>>(pcnt);
    // 4. fused logits(tf32x3 mma) + shuffle softmax + argmax + counts
    k_attn<<<dim3(NN / 128, BB), 128>>>(key, soft, pidx, pcnt);
    // 5. Mm = p_w @ v_w ; pvb = p_w . v_b (epilogue)
    k_gemm64<0, 0, 3><<<dim3(6, 6), 256>>>(p_w, v_w, pMm, v_b, nullptr, nullptr, ppvb);
    // 6. segment sums of key
    k_seg<<<dim3(NSEG, 3, BB), 128>>>(key);
    // 7. out = (S @ Mm.T + cnt*pvb)/(cnt+1) + p_b
    k_gemm64<2, 1, 2><<<dim3(6, 32), 256>>>(pSp, pMm, out, p_b, pcnt, ppvb, nullptr);
}

// round 13
// speedup vs baseline: 1.8068x; 1.8067x over previous
#include <cuda_runtime.h>
#include <math.h>
#include <stdint.h>

#define BB 32
#define GG 64
#define NN 4096
#define CC 384
#define NSEG 8
#define SCALE 0.051031036307982884f  /* 384^-0.5 */

// ---------------- scratch (device globals; no allocation allowed) ----------------
__device__ float g_qa[BB*GG*CC];     // query @ q_w.T + q_b
__device__ float g_q2[BB*GG*CC];     // qa @ k_w
__device__ float g_Mm[CC*CC];        // p_w @ v_w
__device__ float g_pvb[CC];          // p_w @ v_b
__device__ float g_t[BB*GG];         // qa . k_b  per (b,g)
__device__ int   g_idx[BB*NN];       // argmax group per (b,n)
__device__ int   g_cnt[BB*GG];       // counts per (b,g)
__device__ float g_Sp[(size_t)NSEG*BB*GG*CC]; // n-segment partial key sums

// ---------------- f32x2 packed helpers (sm_103a) ----------------
__device__ __forceinline__ void fma_f32x2(unsigned long long& d, unsigned long long a,
                                          unsigned long long b, unsigned long long c) {
    asm("fma.rn.f32x2 %0, %1, %2, %3;" : "=l"(d) : "l"(a), "l"(b), "l"(c));
}
__device__ __forceinline__ unsigned long long pack2(float lo, float hi) {
    unsigned long long d;
    asm("mov.b64 %0, {%1, %2};" : "=l"(d) : "f"(lo), "f"(hi));
    return d;
}
__device__ __forceinline__ void unpack2(float& lo, float& hi, unsigned long long v) {
    asm("mov.b64 {%0, %1}, %2;" : "=f"(lo), "=f"(hi) : "l"(v));
}

// ---------------- tf32 helpers (mma.sync path; baseline sm_80+ PTX) ----------------
// mask split: hi keeps 10 mantissa bits (valid tf32); lo = x - hi exact.
__device__ __forceinline__ float maskhi(float x) {
    return __uint_as_float(__float_as_uint(x) & 0xFFFFE000u);
}
#define MMA_TF32(d, a, b)                                                       \
    asm volatile("mma.sync.aligned.m16n8k8.row.col.f32.tf32.tf32.f32 "          \
        "{%0,%1,%2,%3}, {%4,%5,%6,%7}, {%8,%9}, {%0,%1,%2,%3};"                 \
        : "+f"((d)[0]), "+f"((d)[1]), "+f"((d)[2]), "+f"((d)[3])                \
        : "r"((a)[0]), "r"((a)[1]), "r"((a)[2]), "r"((a)[3]),                   \
          "r"((b)[0]), "r"((b)[1]))

// ---------------- zero counts ----------------
__global__ void k_zero(int* cnt) {
    int t = blockIdx.x * blockDim.x + threadIdx.x;
    if (t < BB*GG) cnt[t] = 0;
}

// ---------------- generic 64x64-tile fp32 GEMM (f32x2 inner) ----------------
// AM: 0 = A row-major; 2 = row-major sum of NSEG partials
// BM: 0 = B k-major B[k*C+j]; 1 = B n-major B[j*C+k]
// EPI:0 = store; 1 = +bias[j]; 2 = out epilogue ((v+cnt*pvb)/(cnt+1)+bias);
//     3 = plain store + aux[i] = A[i,:].bias (dot-vector epilogue, blockIdx.x==0 writes)
template<int AM, int BM, int EPI>
__global__ void __launch_bounds__(256) k_gemm64(const float* __restrict__ A,
                                                const float* __restrict__ Bm,
                                                float* __restrict__ Cc,
                                                const float* __restrict__ bias,
                                                const int* __restrict__ cnt,
                                                const float* __restrict__ pvb,
                                                float* __restrict__ aux) {
    __shared__ __align__(16) float As[16][68];
    __shared__ __align__(16) float Bs[16][68];
    int j0 = blockIdx.x * 64, i0 = blockIdx.y * 64;
    int tid = threadIdx.x;
    unsigned long long acc2[4][2];
    #pragma unroll
    for (int i = 0; i < 4; i++) { acc2[i][0] = 0ULL; acc2[i][1] = 0ULL; }
    float tacc = 0.f;
    for (int k0 = 0; k0 < CC; k0 += 16) {
        {
            int r = tid >> 2, kq = (tid & 3) * 4;
            float4 v;
            if (AM == 2) {
                const float* p = &A[(size_t)(i0 + r) * CC + k0 + kq];
                const size_t PS = (size_t)BB * GG * CC;
                float4 s = *(const float4*)p;
                #pragma unroll
                for (int q = 1; q < NSEG; q++) {
                    float4 vq = *(const float4*)(p + (size_t)q * PS);
                    s.x += vq.x; s.y += vq.y; s.z += vq.z; s.w += vq.w;
                }
                v = s;
            } else {
                v = *(const float4*)&A[(size_t)(i0 + r) * CC + k0 + kq];
            }
            As[kq + 0][r] = v.x; As[kq + 1][r] = v.y;
            As[kq + 2][r] = v.z; As[kq + 3][r] = v.w;
        }
        if (BM == 0) {
            int kk = tid >> 4, j4 = (tid & 15) * 4;
            *(float4*)&Bs[kk][j4] = *(const float4*)&Bm[(size_t)(k0 + kk) * CC + j0 + j4];
        } else {
            int jr = tid >> 2, kq = (tid & 3) * 4;
            float4 v = *(const float4*)&Bm[(size_t)(jr + j0) * CC + k0 + kq];
            Bs[kq + 0][jr] = v.x; Bs[kq + 1][jr] = v.y;
            Bs[kq + 2][jr] = v.z; Bs[kq + 3][jr] = v.w;
        }
        __syncthreads();
        if (EPI == 3) {
            if (tid < 64) {
                #pragma unroll
                for (int kk = 0; kk < 16; kk++)
                    tacc += As[kk][tid] * bias[k0 + kk];
            }
        }
        int ty = tid >> 4, tx = tid & 15;
        #pragma unroll
        for (int kk = 0; kk < 16; kk++) {
            float4 a4 = *(const float4*)&As[kk][ty * 4];
            ulonglong2 bb = *(const ulonglong2*)&Bs[kk][tx * 4];
            unsigned long long av[4] = {pack2(a4.x, a4.x), pack2(a4.y, a4.y),
                                        pack2(a4.z, a4.z), pack2(a4.w, a4.w)};
            #pragma unroll
            for (int i = 0; i < 4; i++) {
                fma_f32x2(acc2[i][0], av[i], bb.x, acc2[i][0]);
                fma_f32x2(acc2[i][1], av[i], bb.y, acc2[i][1]);
            }
        }
        __syncthreads();
    }
    int ty = tid >> 4, tx = tid & 15;
    #pragma unroll
    for (int i = 0; i < 4; i++) {
        int r = i0 + ty * 4 + i;
        float a0, a1, a2, a3;
        unpack2(a0, a1, acc2[i][0]);
        unpack2(a2, a3, acc2[i][1]);
        float accv[4] = {a0, a1, a2, a3};
        #pragma unroll
        for (int j = 0; j < 4; j++) {
            int c = j0 + tx * 4 + j;
            float v = accv[j];
            if (EPI == 1) v += bias[c];
            if (EPI == 2) {
                float cf = (float)cnt[r];
                v = (v + cf * pvb[c]) / (cf + 1.0f) + bias[c];
            }
            Cc[(size_t)r * CC + c] = v;
        }
    }
    if (EPI == 3) {
        if (blockIdx.x == 0 && tid < 64) aux[i0 + tid] = tacc;
    }
}

// ===== fused logits (tf32x3 mma.sync) + shuffle softmax(over G) + argmax + counts =====
// Block: one b, 128-n tile, all 64 g. 128 threads = 4 warps.
// RAW fp32 in smem (13.3KB); hi/lo mask-split happens at fragment-load time in
// registers (halves LDS+STS vs split-in-smem). B columns XOR-swizzled:
// col' = col ^ ((row&12)<<1) -> STS banks 8i+nn+{0,8,16,24}: conflict-free.
// Epilogue: shfl_xor butterflies (lanes xor 4/8/16) per column; no smem staging.
__global__ void __launch_bounds__(128) k_attn(const float* __restrict__ key,
                                              float* __restrict__ soft,
                                              int* __restrict__ idxp,
                                              int* __restrict__ cntp) {
    __shared__ __align__(16) float sA[16][72];    // raw q2 (k-major)
    __shared__ __align__(16) float sB[16][136];   // raw key (k-major, swizzled cols)
    __shared__ float tsm[GG];

    int b = blockIdx.y;
    int n_base = blockIdx.x * 128;
    int tid = threadIdx.x, lane = tid & 31, warp = tid >> 5;
    if (tid < GG) tsm[tid] = g_t[b * GG + tid];

    const float* q2 = g_q2 + (size_t)b * GG * CC;
    const float* kp = key + ((size_t)b * NN + n_base) * CC;

    float acc[4][4][4];
    #pragma unroll
    for (int mt = 0; mt < 4; mt++)
        #pragma unroll
        for (int nt = 0; nt < 4; nt++)
            #pragma unroll
            for (int r = 0; r < 4; r++) acc[mt][nt][r] = 0.f;

    int kr = lane & 3, gr = lane >> 2;
    int wb = warp * 32;

    for (int k0 = 0; k0 < CC; k0 += 16) {
        {   // A (q2): 64g x 16k raw
            int g = tid >> 1, ks = (tid & 1) * 8;
            float4 v0 = *(const float4*)&q2[(size_t)g * CC + k0 + ks];
            float4 v1 = *(const float4*)&q2[(size_t)g * CC + k0 + ks + 4];
            float f[8] = {v0.x, v0.y, v0.z, v0.w, v1.x, v1.y, v1.z, v1.w};
            #pragma unroll
            for (int i = 0; i < 8; i++) sA[ks + i][g] = f[i];
        }
        #pragma unroll
        for (int p = 0; p < 4; p++) {  // B (key): 128n x 16k raw, swizzled cols
            int nn = (tid >> 2) + p * 32, kq = (tid & 3) * 4;
            float4 v = *(const float4*)&kp[(size_t)nn * CC + k0 + kq];
            float f[4] = {v.x, v.y, v.z, v.w};
            #pragma unroll
            for (int i = 0; i < 4; i++) {
                int r = kq + i;
                sB[r][nn ^ ((r & 12) << 1)] = f[i];
            }
        }
        __syncthreads();
        #pragma unroll
        for (int s = 0; s < 2; s++) {
            int k1 = s * 8 + kr, k2 = k1 + 4;
            int c1 = (k1 & 12) << 1, c2x = (k2 & 12) << 1;   // B col swizzle consts
            uint32_t bh[4][2], bl[4][2];
            #pragma unroll
            for (int nt = 0; nt < 4; nt++) {
                int nc = wb + nt * 8 + gr;
                float b0 = sB[k1][nc ^ c1];
                float b1 = sB[k2][nc ^ c2x];
                float h0 = maskhi(b0), h1 = maskhi(b1);
                bh[nt][0] = __float_as_uint(h0); bl[nt][0] = __float_as_uint(b0 - h0);
                bh[nt][1] = __float_as_uint(h1); bl[nt][1] = __float_as_uint(b1 - h1);
            }
            #pragma unroll
            for (int mt = 0; mt < 4; mt++) {
                int g0 = mt * 16 + gr;
                float a0 = sA[k1][g0], a1 = sA[k1][g0 + 8];
                float a2 = sA[k2][g0], a3 = sA[k2][g0 + 8];
                float h0 = maskhi(a0), h1 = maskhi(a1), h2 = maskhi(a2), h3 = maskhi(a3);
                uint32_t ah[4] = {__float_as_uint(h0), __float_as_uint(h1),
                                  __float_as_uint(h2), __float_as_uint(h3)};
                uint32_t al[4] = {__float_as_uint(a0 - h0), __float_as_uint(a1 - h1),
                                  __float_as_uint(a2 - h2), __float_as_uint(a3 - h3)};
                #pragma unroll
                for (int nt = 0; nt < 4; nt++) {
                    MMA_TF32(acc[mt][nt], ah, bh[nt]);
                    MMA_TF32(acc[mt][nt], ah, bl[nt]);
                    MMA_TF32(acc[mt][nt], al, bh[nt]);
                }
            }
        }
        __syncthreads();
    }

    // ---- shuffle-based softmax/argmax epilogue (no smem staging) ----
    float tv0[4], tv1[4];
    #pragma unroll
    for (int mt = 0; mt < 4; mt++) { tv0[mt] = tsm[16 * mt + gr]; tv1[mt] = tsm[16 * mt + 8 + gr]; }

    float* softb = soft + (size_t)b * GG * NN;
    #pragma unroll
    for (int nt = 0; nt < 4; nt++) {
        float e[2][8]; int am[2]; float inv[2];
        #pragma unroll
        for (int p = 0; p < 2; p++) {
            float l[8];
            #pragma unroll
            for (int mt = 0; mt < 4; mt++) {
                l[2 * mt]     = SCALE * (acc[mt][nt][p]     + tv0[mt]);
                l[2 * mt + 1] = SCALE * (acc[mt][nt][2 + p] + tv1[mt]);
            }
            // local first-max (ascending g: i -> g = 16*(i/2) + 8*(i&1) + gr)
            float m = l[0]; int a = gr;
            #pragma unroll
            for (int i = 1; i < 8; i++) {
                int gi = 16 * (i >> 1) + 8 * (i & 1) + gr;
                if (l[i] > m) { m = l[i]; a = gi; }
            }
            // cross-lane reduce over gr (lanes xor 4,8,16); tie -> lowest g
            #pragma unroll
            for (int o = 4; o <= 16; o <<= 1) {
                float mo = __shfl_xor_sync(0xFFFFFFFFu, m, o);
                int   ao = __shfl_xor_sync(0xFFFFFFFFu, a, o);
                if (mo > m || (mo == m && ao < a)) { m = mo; a = ao; }
            }
            float s = 0.f;
            #pragma unroll
            for (int i = 0; i < 8; i++) { e[p][i] = __expf(l[i] - m); s += e[p][i]; }
            #pragma unroll
            for (int o = 4; o <= 16; o <<= 1) s += __shfl_xor_sync(0xFFFFFFFFu, s, o);
            inv[p] = 1.0f / s; am[p] = a;
        }
        int cb = n_base + wb + nt * 8 + 2 * kr;
        #pragma unroll
        for (int mt = 0; mt < 4; mt++) {
            int g0 = 16 * mt + gr, g1 = g0 + 8;
            *(float2*)&softb[(size_t)g0 * NN + cb] =
                make_float2(e[0][2 * mt] * inv[0], e[1][2 * mt] * inv[1]);
            *(float2*)&softb[(size_t)g1 * NN + cb] =
                make_float2(e[0][2 * mt + 1] * inv[0], e[1][2 * mt + 1] * inv[1]);
        }
        if (gr == 0) {
            idxp[b * NN + cb]     = am[0];
            idxp[b * NN + cb + 1] = am[1];
            atomicAdd(&cntp[b * GG + am[0]], 1);
            atomicAdd(&cntp[b * GG + am[1]], 1);
        }
    }
}

// ---------------- segment sums of key rows by argmax group ----------------
__global__ void __launch_bounds__(128) k_seg(const float* __restrict__ key) {
    __shared__ float S[GG][128];
    __shared__ int sidx[512];
    int ns = blockIdx.x, cb = blockIdx.y, b = blockIdx.z;
    int tid = threadIdx.x;
    int c0 = cb * 128, nb = ns * 512;
    for (int i = tid; i < GG * 128; i += 128) ((float*)S)[i] = 0.f;
    for (int i = tid; i < 512; i += 128) sidx[i] = g_idx[b * NN + nb + i];
    __syncthreads();
    const float* kp = key + ((size_t)(b * NN + nb)) * CC + c0;
    for (int n = 0; n < 512; n += 8) {
        float x[8];
        #pragma unroll
        for (int i = 0; i < 8; i++) x[i] = kp[(size_t)(n + i) * CC + tid];
        #pragma unroll
        for (int i = 0; i < 8; i++) S[sidx[n + i]][tid] += x[i];
    }
    __syncthreads();
    float* dst = g_Sp + (size_t)ns * BB * GG * CC + (size_t)b * GG * CC + c0 + tid;
    for (int g = 0; g < GG; g++) dst[(size_t)g * CC] = S[g][tid];
}

// ---------------- launcher ----------------
extern "C" void kernel_launch(void* const* d_in, const int* in_sizes, int n_in,
                              void* d_out, int out_size) {
    const float* query = (const float*)d_in[0];
    const float* key   = (const float*)d_in[1];
    const float* q_w   = (const float*)d_in[2];
    const float* q_b   = (const float*)d_in[3];
    const float* k_w   = (const float*)d_in[4];
    const float* k_b   = (const float*)d_in[5];
    const float* v_w   = (const float*)d_in[6];
    const float* v_b   = (const float*)d_in[7];
    const float* p_w   = (const float*)d_in[8];
    const float* p_b   = (const float*)d_in[9];
    (void)n_in; (void)in_sizes;

    float* out  = (float*)d_out;
    float* soft = out + ((size_t)out_size - (size_t)BB * GG * NN);

    float *pqa, *pq2, *pMm, *ppvb, *pSp, *pt;
    int *pidx, *pcnt;
    cudaGetSymbolAddress((void**)&pqa,  g_qa);
    cudaGetSymbolAddress((void**)&pq2,  g_q2);
    cudaGetSymbolAddress((void**)&pMm,  g_Mm);
    cudaGetSymbolAddress((void**)&ppvb, g_pvb);
    cudaGetSymbolAddress((void**)&pSp,  g_Sp);
    cudaGetSymbolAddress((void**)&pt,   g_t);
    cudaGetSymbolAddress((void**)&pidx, g_idx);
    cudaGetSymbolAddress((void**)&pcnt, g_cnt);

    // 1. qa = query @ q_w.T + q_b
    k_gemm64<0, 1, 1><<<dim3(6, 32), 256>>>(query, q_w, pqa, q_b, nullptr, nullptr, nullptr);
    // 2. q2 = qa @ k_w ; t = qa . k_b (epilogue)
    k_gemm64<0, 0, 3><<<dim3(6, 32), 256>>>(pqa, k_w, pq2, k_b, nullptr, nullptr, pt);
    // 3. zero counts (independent; placed here so k_attn is capture slot #4)
    k_zero<<<2, 1024>>>(pcnt);
    // 4. fused logits(tf32x3 mma, raw-smem split-on-load) + shuffle softmax + argmax + counts
    k_attn<<<dim3(NN / 128, BB), 128>>>(key, soft, pidx, pcnt);
    // 5. Mm = p_w @ v_w ; pvb = p_w . v_b (epilogue)
    k_gemm64<0, 0, 3><<<dim3(6, 6), 256>>>(p_w, v_w, pMm, v_b, nullptr, nullptr, ppvb);
    // 6. segment sums of key
    k_seg<<<dim3(NSEG, 3, BB), 128>>>(key);
    // 7. out = (S @ Mm.T + cnt*pvb)/(cnt+1) + p_b
    k_gemm64<2, 1, 2><<<dim3(6, 32), 256>>>(pSp, pMm, out, p_b, pcnt, ppvb, nullptr);
}

// round 14
// speedup vs baseline: 1.8432x; 1.0202x over previous
#include <cuda_runtime.h>
#include <math.h>
#include <stdint.h>

#define BB 32
#define GG 64
#define NN 4096
#define CC 384
#define NSEG 8
#define SCALE 0.051031036307982884f  /* 384^-0.5 */

// ---------------- scratch (device globals; no allocation allowed) ----------------
__device__ float g_qa[BB*GG*CC];     // query @ q_w.T + q_b
__device__ float g_q2[BB*GG*CC];     // qa @ k_w
__device__ float g_Mm[CC*CC];        // p_w @ v_w
__device__ float g_pvb[CC];          // p_w @ v_b
__device__ float g_t[BB*GG];         // qa . k_b  per (b,g)
__device__ int   g_idx[BB*NN];       // argmax group per (b,n)
__device__ int   g_cnt[BB*GG];       // counts per (b,g)
__device__ float g_Sp[(size_t)NSEG*BB*GG*CC]; // n-segment partial key sums

// ---------------- f32x2 packed helpers (sm_103a) ----------------
__device__ __forceinline__ void fma_f32x2(unsigned long long& d, unsigned long long a,
                                          unsigned long long b, unsigned long long c) {
    asm("fma.rn.f32x2 %0, %1, %2, %3;" : "=l"(d) : "l"(a), "l"(b), "l"(c));
}
__device__ __forceinline__ unsigned long long pack2(float lo, float hi) {
    unsigned long long d;
    asm("mov.b64 %0, {%1, %2};" : "=l"(d) : "f"(lo), "f"(hi));
    return d;
}
__device__ __forceinline__ void unpack2(float& lo, float& hi, unsigned long long v) {
    asm("mov.b64 {%0, %1}, %2;" : "=f"(lo), "=f"(hi) : "l"(v));
}

// ---------------- tf32 helpers (mma.sync path; baseline sm_80+ PTX) ----------------
// mask split: hi keeps 10 mantissa bits (valid tf32); lo = x - hi exact.
__device__ __forceinline__ float maskhi(float x) {
    return __uint_as_float(__float_as_uint(x) & 0xFFFFE000u);
}
#define MMA_TF32(d, a, b)                                                       \
    asm volatile("mma.sync.aligned.m16n8k8.row.col.f32.tf32.tf32.f32 "          \
        "{%0,%1,%2,%3}, {%4,%5,%6,%7}, {%8,%9}, {%0,%1,%2,%3};"                 \
        : "+f"((d)[0]), "+f"((d)[1]), "+f"((d)[2]), "+f"((d)[3])                \
        : "r"((a)[0]), "r"((a)[1]), "r"((a)[2]), "r"((a)[3]),                   \
          "r"((b)[0]), "r"((b)[1]))

// ---------------- generic 64x64-tile fp32 GEMM (f32x2 inner) ----------------
// AM: 0 = A row-major; 2 = row-major sum of NSEG partials
// BM: 0 = B k-major B[k*C+j]; 1 = B n-major B[j*C+k]
// EPI:0 = store; 1 = +bias[j]; 2 = out epilogue ((v+cnt*pvb)/(cnt+1)+bias);
//     3 = plain store + aux[i] = A[i,:].bias (x==0) + cnt[i]=0 (x==1)
template<int AM, int BM, int EPI>
__global__ void __launch_bounds__(256) k_gemm64(const float* __restrict__ A,
                                                const float* __restrict__ Bm,
                                                float* __restrict__ Cc,
                                                const float* __restrict__ bias,
                                                int* __restrict__ cnt,
                                                const float* __restrict__ pvb,
                                                float* __restrict__ aux) {
    __shared__ __align__(16) float As[16][68];
    __shared__ __align__(16) float Bs[16][68];
    int j0 = blockIdx.x * 64, i0 = blockIdx.y * 64;
    int tid = threadIdx.x;
    unsigned long long acc2[4][2];
    #pragma unroll
    for (int i = 0; i < 4; i++) { acc2[i][0] = 0ULL; acc2[i][1] = 0ULL; }
    float tacc = 0.f;
    if (EPI == 3 && cnt != nullptr) {
        if (blockIdx.x == 1 && tid < 64) cnt[i0 + tid] = 0;
    }
    for (int k0 = 0; k0 < CC; k0 += 16) {
        {
            int r = tid >> 2, kq = (tid & 3) * 4;
            float4 v;
            if (AM == 2) {
                const float* p = &A[(size_t)(i0 + r) * CC + k0 + kq];
                const size_t PS = (size_t)BB * GG * CC;
                float4 s = *(const float4*)p;
                #pragma unroll
                for (int q = 1; q < NSEG; q++) {
                    float4 vq = *(const float4*)(p + (size_t)q * PS);
                    s.x += vq.x; s.y += vq.y; s.z += vq.z; s.w += vq.w;
                }
                v = s;
            } else {
                v = *(const float4*)&A[(size_t)(i0 + r) * CC + k0 + kq];
            }
            As[kq + 0][r] = v.x; As[kq + 1][r] = v.y;
            As[kq + 2][r] = v.z; As[kq + 3][r] = v.w;
        }
        if (BM == 0) {
            int kk = tid >> 4, j4 = (tid & 15) * 4;
            *(float4*)&Bs[kk][j4] = *(const float4*)&Bm[(size_t)(k0 + kk) * CC + j0 + j4];
        } else {
            int jr = tid >> 2, kq = (tid & 3) * 4;
            float4 v = *(const float4*)&Bm[(size_t)(jr + j0) * CC + k0 + kq];
            Bs[kq + 0][jr] = v.x; Bs[kq + 1][jr] = v.y;
            Bs[kq + 2][jr] = v.z; Bs[kq + 3][jr] = v.w;
        }
        __syncthreads();
        if (EPI == 3) {
            if (tid < 64) {
                #pragma unroll
                for (int kk = 0; kk < 16; kk++)
                    tacc += As[kk][tid] * bias[k0 + kk];
            }
        }
        int ty = tid >> 4, tx = tid & 15;
        #pragma unroll
        for (int kk = 0; kk < 16; kk++) {
            float4 a4 = *(const float4*)&As[kk][ty * 4];
            ulonglong2 bb = *(const ulonglong2*)&Bs[kk][tx * 4];
            unsigned long long av[4] = {pack2(a4.x, a4.x), pack2(a4.y, a4.y),
                                        pack2(a4.z, a4.z), pack2(a4.w, a4.w)};
            #pragma unroll
            for (int i = 0; i < 4; i++) {
                fma_f32x2(acc2[i][0], av[i], bb.x, acc2[i][0]);
                fma_f32x2(acc2[i][1], av[i], bb.y, acc2[i][1]);
            }
        }
        __syncthreads();
    }
    int ty = tid >> 4, tx = tid & 15;
    #pragma unroll
    for (int i = 0; i < 4; i++) {
        int r = i0 + ty * 4 + i;
        float a0, a1, a2, a3;
        unpack2(a0, a1, acc2[i][0]);
        unpack2(a2, a3, acc2[i][1]);
        float accv[4] = {a0, a1, a2, a3};
        #pragma unroll
        for (int j = 0; j < 4; j++) {
            int c = j0 + tx * 4 + j;
            float v = accv[j];
            if (EPI == 1) v += bias[c];
            if (EPI == 2) {
                float cf = (float)cnt[r];
                v = (v + cf * pvb[c]) / (cf + 1.0f) + bias[c];
            }
            Cc[(size_t)r * CC + c] = v;
        }
    }
    if (EPI == 3) {
        if (blockIdx.x == 0 && tid < 64) aux[i0 + tid] = tacc;
    }
}

// ===== fused logits (tf32x3 mma.sync) + shuffle softmax(over G) + argmax + counts =====
// IDENTICAL to R13's measured-112us kernel.
__global__ void __launch_bounds__(128) k_attn(const float* __restrict__ key,
                                              float* __restrict__ soft,
                                              int* __restrict__ idxp,
                                              int* __restrict__ cntp) {
    __shared__ __align__(16) float sA[16][72];    // raw q2 (k-major)
    __shared__ __align__(16) float sB[16][136];   // raw key (k-major, swizzled cols)
    __shared__ float tsm[GG];

    int b = blockIdx.y;
    int n_base = blockIdx.x * 128;
    int tid = threadIdx.x, lane = tid & 31, warp = tid >> 5;
    if (tid < GG) tsm[tid] = g_t[b * GG + tid];

    const float* q2 = g_q2 + (size_t)b * GG * CC;
    const float* kp = key + ((size_t)b * NN + n_base) * CC;

    float acc[4][4][4];
    #pragma unroll
    for (int mt = 0; mt < 4; mt++)
        #pragma unroll
        for (int nt = 0; nt < 4; nt++)
            #pragma unroll
            for (int r = 0; r < 4; r++) acc[mt][nt][r] = 0.f;

    int kr = lane & 3, gr = lane >> 2;
    int wb = warp * 32;

    for (int k0 = 0; k0 < CC; k0 += 16) {
        {   // A (q2): 64g x 16k raw
            int g = tid >> 1, ks = (tid & 1) * 8;
            float4 v0 = *(const float4*)&q2[(size_t)g * CC + k0 + ks];
            float4 v1 = *(const float4*)&q2[(size_t)g * CC + k0 + ks + 4];
            float f[8] = {v0.x, v0.y, v0.z, v0.w, v1.x, v1.y, v1.z, v1.w};
            #pragma unroll
            for (int i = 0; i < 8; i++) sA[ks + i][g] = f[i];
        }
        #pragma unroll
        for (int p = 0; p < 4; p++) {  // B (key): 128n x 16k raw, swizzled cols
            int nn = (tid >> 2) + p * 32, kq = (tid & 3) * 4;
            float4 v = *(const float4*)&kp[(size_t)nn * CC + k0 + kq];
            float f[4] = {v.x, v.y, v.z, v.w};
            #pragma unroll
            for (int i = 0; i < 4; i++) {
                int r = kq + i;
                sB[r][nn ^ ((r & 12) << 1)] = f[i];
            }
        }
        __syncthreads();
        #pragma unroll
        for (int s = 0; s < 2; s++) {
            int k1 = s * 8 + kr, k2 = k1 + 4;
            int c1 = (k1 & 12) << 1, c2x = (k2 & 12) << 1;
            uint32_t bh[4][2], bl[4][2];
            #pragma unroll
            for (int nt = 0; nt < 4; nt++) {
                int nc = wb + nt * 8 + gr;
                float b0 = sB[k1][nc ^ c1];
                float b1 = sB[k2][nc ^ c2x];
                float h0 = maskhi(b0), h1 = maskhi(b1);
                bh[nt][0] = __float_as_uint(h0); bl[nt][0] = __float_as_uint(b0 - h0);
                bh[nt][1] = __float_as_uint(h1); bl[nt][1] = __float_as_uint(b1 - h1);
            }
            #pragma unroll
            for (int mt = 0; mt < 4; mt++) {
                int g0 = mt * 16 + gr;
                float a0 = sA[k1][g0], a1 = sA[k1][g0 + 8];
                float a2 = sA[k2][g0], a3 = sA[k2][g0 + 8];
                float h0 = maskhi(a0), h1 = maskhi(a1), h2 = maskhi(a2), h3 = maskhi(a3);
                uint32_t ah[4] = {__float_as_uint(h0), __float_as_uint(h1),
                                  __float_as_uint(h2), __float_as_uint(h3)};
                uint32_t al[4] = {__float_as_uint(a0 - h0), __float_as_uint(a1 - h1),
                                  __float_as_uint(a2 - h2), __float_as_uint(a3 - h3)};
                #pragma unroll
                for (int nt = 0; nt < 4; nt++) {
                    MMA_TF32(acc[mt][nt], ah, bh[nt]);
                    MMA_TF32(acc[mt][nt], ah, bl[nt]);
                    MMA_TF32(acc[mt][nt], al, bh[nt]);
                }
            }
        }
        __syncthreads();
    }

    // ---- shuffle-based softmax/argmax epilogue (no smem staging) ----
    float tv0[4], tv1[4];
    #pragma unroll
    for (int mt = 0; mt < 4; mt++) { tv0[mt] = tsm[16 * mt + gr]; tv1[mt] = tsm[16 * mt + 8 + gr]; }

    float* softb = soft + (size_t)b * GG * NN;
    #pragma unroll
    for (int nt = 0; nt < 4; nt++) {
        float e[2][8]; int am[2]; float inv[2];
        #pragma unroll
        for (int p = 0; p < 2; p++) {
            float l[8];
            #pragma unroll
            for (int mt = 0; mt < 4; mt++) {
                l[2 * mt]     = SCALE * (acc[mt][nt][p]     + tv0[mt]);
                l[2 * mt + 1] = SCALE * (acc[mt][nt][2 + p] + tv1[mt]);
            }
            float m = l[0]; int a = gr;
            #pragma unroll
            for (int i = 1; i < 8; i++) {
                int gi = 16 * (i >> 1) + 8 * (i & 1) + gr;
                if (l[i] > m) { m = l[i]; a = gi; }
            }
            #pragma unroll
            for (int o = 4; o <= 16; o <<= 1) {
                float mo = __shfl_xor_sync(0xFFFFFFFFu, m, o);
                int   ao = __shfl_xor_sync(0xFFFFFFFFu, a, o);
                if (mo > m || (mo == m && ao < a)) { m = mo; a = ao; }
            }
            float s = 0.f;
            #pragma unroll
            for (int i = 0; i < 8; i++) { e[p][i] = __expf(l[i] - m); s += e[p][i]; }
            #pragma unroll
            for (int o = 4; o <= 16; o <<= 1) s += __shfl_xor_sync(0xFFFFFFFFu, s, o);
            inv[p] = 1.0f / s; am[p] = a;
        }
        int cb = n_base + wb + nt * 8 + 2 * kr;
        #pragma unroll
        for (int mt = 0; mt < 4; mt++) {
            int g0 = 16 * mt + gr, g1 = g0 + 8;
            *(float2*)&softb[(size_t)g0 * NN + cb] =
                make_float2(e[0][2 * mt] * inv[0], e[1][2 * mt] * inv[1]);
            *(float2*)&softb[(size_t)g1 * NN + cb] =
                make_float2(e[0][2 * mt + 1] * inv[0], e[1][2 * mt + 1] * inv[1]);
        }
        if (gr == 0) {
            idxp[b * NN + cb]     = am[0];
            idxp[b * NN + cb + 1] = am[1];
            atomicAdd(&cntp[b * GG + am[0]], 1);
            atomicAdd(&cntp[b * GG + am[1]], 1);
        }
    }
}

// ---------------- segment sums of key rows by argmax group ----------------
__global__ void __launch_bounds__(128) k_seg(const float* __restrict__ key) {
    __shared__ float S[GG][128];
    __shared__ int sidx[512];
    int ns = blockIdx.x, cb = blockIdx.y, b = blockIdx.z;
    int tid = threadIdx.x;
    int c0 = cb * 128, nb = ns * 512;
    for (int i = tid; i < GG * 128; i += 128) ((float*)S)[i] = 0.f;
    for (int i = tid; i < 512; i += 128) sidx[i] = g_idx[b * NN + nb + i];
    __syncthreads();
    const float* kp = key + ((size_t)(b * NN + nb)) * CC + c0;
    for (int n = 0; n < 512; n += 8) {
        float x[8];
        #pragma unroll
        for (int i = 0; i < 8; i++) x[i] = kp[(size_t)(n + i) * CC + tid];
        #pragma unroll
        for (int i = 0; i < 8; i++) S[sidx[n + i]][tid] += x[i];
    }
    __syncthreads();
    float* dst = g_Sp + (size_t)ns * BB * GG * CC + (size_t)b * GG * CC + c0 + tid;
    for (int g = 0; g < GG; g++) dst[(size_t)g * CC] = S[g][tid];
}

// ---------------- launcher ----------------
extern "C" void kernel_launch(void* const* d_in, const int* in_sizes, int n_in,
                              void* d_out, int out_size) {
    const float* query = (const float*)d_in[0];
    const float* key   = (const float*)d_in[1];
    const float* q_w   = (const float*)d_in[2];
    const float* q_b   = (const float*)d_in[3];
    const float* k_w   = (const float*)d_in[4];
    const float* k_b   = (const float*)d_in[5];
    const float* v_w   = (const float*)d_in[6];
    const float* v_b   = (const float*)d_in[7];
    const float* p_w   = (const float*)d_in[8];
    const float* p_b   = (const float*)d_in[9];
    (void)n_in; (void)in_sizes;

    float* out  = (float*)d_out;
    float* soft = out + ((size_t)out_size - (size_t)BB * GG * NN);

    float *pqa, *pq2, *pMm, *ppvb, *pSp, *pt;
    int *pidx, *pcnt;
    cudaGetSymbolAddress((void**)&pqa,  g_qa);
    cudaGetSymbolAddress((void**)&pq2,  g_q2);
    cudaGetSymbolAddress((void**)&pMm,  g_Mm);
    cudaGetSymbolAddress((void**)&ppvb, g_pvb);
    cudaGetSymbolAddress((void**)&pSp,  g_Sp);
    cudaGetSymbolAddress((void**)&pt,   g_t);
    cudaGetSymbolAddress((void**)&pidx, g_idx);
    cudaGetSymbolAddress((void**)&pcnt, g_cnt);

    // 1. qa = query @ q_w.T + q_b
    k_gemm64<0, 1, 1><<<dim3(6, 32), 256>>>(query, q_w, pqa, q_b, nullptr, nullptr, nullptr);
    // 2. q2 = qa @ k_w ; t = qa . k_b (x==0) ; cnt = 0 (x==1)
    k_gemm64<0, 0, 3><<<dim3(6, 32), 256>>>(pqa, k_w, pq2, k_b, pcnt, nullptr, pt);
    // 3. fused logits(tf32x3 mma) + shuffle softmax + argmax + counts
    k_attn<<<dim3(NN / 128, BB), 128>>>(key, soft, pidx, pcnt);
    // 4. segment sums of key   <- ncu captures launch #4 this round
    k_seg<<<dim3(NSEG, 3, BB), 128>>>(key);
    // 5. Mm = p_w @ v_w ; pvb = p_w . v_b
    k_gemm64<0, 0, 3><<<dim3(6, 6), 256>>>(p_w, v_w, pMm, v_b, nullptr, nullptr, ppvb);
    // 6. out = (S @ Mm.T + cnt*pvb)/(cnt+1) + p_b
    k_gemm64<2, 1, 2><<<dim3(6, 32), 256>>>(pSp, pMm, out, p_b, pcnt, ppvb, nullptr);
}

// round 15
// speedup vs baseline: 2.0032x; 1.0868x over previous
#include <cuda_runtime.h>
#include <math.h>
#include <stdint.h>

#define BB 32
#define GG 64
#define NN 4096
#define CC 384
#define NSEG 16
#define NR (NN / NSEG)   /* 256 rows per segment */
#define SCALE 0.051031036307982884f  /* 384^-0.5 */

// ---------------- scratch (device globals; no allocation allowed) ----------------
__device__ float g_qa[BB*GG*CC];     // query @ q_w.T + q_b
__device__ float g_q2[BB*GG*CC];     // qa @ k_w
__device__ float g_Mm[CC*CC];        // p_w @ v_w
__device__ float g_pvb[CC];          // p_w @ v_b
__device__ float g_t[BB*GG];         // qa . k_b  per (b,g)
__device__ int   g_idx[BB*NN];       // argmax group per (b,n)
__device__ int   g_cnt[BB*GG];       // counts per (b,g)
__device__ float g_Sp[(size_t)NSEG*BB*GG*CC]; // n-segment partial key sums
__device__ float g_S[BB*GG*CC];      // reduced key segment sums

// ---------------- f32x2 packed helpers (sm_103a) ----------------
__device__ __forceinline__ void fma_f32x2(unsigned long long& d, unsigned long long a,
                                          unsigned long long b, unsigned long long c) {
    asm("fma.rn.f32x2 %0, %1, %2, %3;" : "=l"(d) : "l"(a), "l"(b), "l"(c));
}
__device__ __forceinline__ unsigned long long pack2(float lo, float hi) {
    unsigned long long d;
    asm("mov.b64 %0, {%1, %2};" : "=l"(d) : "f"(lo), "f"(hi));
    return d;
}
__device__ __forceinline__ void unpack2(float& lo, float& hi, unsigned long long v) {
    asm("mov.b64 {%0, %1}, %2;" : "=f"(lo), "=f"(hi) : "l"(v));
}

// ---------------- tf32 helpers (mma.sync path; baseline sm_80+ PTX) ----------------
// mask split: hi keeps 10 mantissa bits (valid tf32); lo = x - hi exact.
__device__ __forceinline__ float maskhi(float x) {
    return __uint_as_float(__float_as_uint(x) & 0xFFFFE000u);
}
#define MMA_TF32(d, a, b)                                                       \
    asm volatile("mma.sync.aligned.m16n8k8.row.col.f32.tf32.tf32.f32 "          \
        "{%0,%1,%2,%3}, {%4,%5,%6,%7}, {%8,%9}, {%0,%1,%2,%3};"                 \
        : "+f"((d)[0]), "+f"((d)[1]), "+f"((d)[2]), "+f"((d)[3])                \
        : "r"((a)[0]), "r"((a)[1]), "r"((a)[2]), "r"((a)[3]),                   \
          "r"((b)[0]), "r"((b)[1]))

// ---------------- generic 64x64-tile fp32 GEMM (f32x2 inner) ----------------
// AM: 0 = A row-major
// BM: 0 = B k-major B[k*C+j]; 1 = B n-major B[j*C+k]
// EPI:0 = store; 1 = +bias[j]; 2 = out epilogue ((v+cnt*pvb)/(cnt+1)+bias);
//     3 = plain store + aux[i] = A[i,:].bias (x==0) + cnt[i]=0 (x==1)
template<int AM, int BM, int EPI>
__global__ void __launch_bounds__(256) k_gemm64(const float* __restrict__ A,
                                                const float* __restrict__ Bm,
                                                float* __restrict__ Cc,
                                                const float* __restrict__ bias,
                                                int* __restrict__ cnt,
                                                const float* __restrict__ pvb,
                                                float* __restrict__ aux) {
    __shared__ __align__(16) float As[16][68];
    __shared__ __align__(16) float Bs[16][68];
    int j0 = blockIdx.x * 64, i0 = blockIdx.y * 64;
    int tid = threadIdx.x;
    unsigned long long acc2[4][2];
    #pragma unroll
    for (int i = 0; i < 4; i++) { acc2[i][0] = 0ULL; acc2[i][1] = 0ULL; }
    float tacc = 0.f;
    if (EPI == 3 && cnt != nullptr) {
        if (blockIdx.x == 1 && tid < 64) cnt[i0 + tid] = 0;
    }
    for (int k0 = 0; k0 < CC; k0 += 16) {
        {
            int r = tid >> 2, kq = (tid & 3) * 4;
            float4 v = *(const float4*)&A[(size_t)(i0 + r) * CC + k0 + kq];
            As[kq + 0][r] = v.x; As[kq + 1][r] = v.y;
            As[kq + 2][r] = v.z; As[kq + 3][r] = v.w;
        }
        if (BM == 0) {
            int kk = tid >> 4, j4 = (tid & 15) * 4;
            *(float4*)&Bs[kk][j4] = *(const float4*)&Bm[(size_t)(k0 + kk) * CC + j0 + j4];
        } else {
            int jr = tid >> 2, kq = (tid & 3) * 4;
            float4 v = *(const float4*)&Bm[(size_t)(jr + j0) * CC + k0 + kq];
            Bs[kq + 0][jr] = v.x; Bs[kq + 1][jr] = v.y;
            Bs[kq + 2][jr] = v.z; Bs[kq + 3][jr] = v.w;
        }
        __syncthreads();
        if (EPI == 3) {
            if (tid < 64) {
                #pragma unroll
                for (int kk = 0; kk < 16; kk++)
                    tacc += As[kk][tid] * bias[k0 + kk];
            }
        }
        int ty = tid >> 4, tx = tid & 15;
        #pragma unroll
        for (int kk = 0; kk < 16; kk++) {
            float4 a4 = *(const float4*)&As[kk][ty * 4];
            ulonglong2 bb = *(const ulonglong2*)&Bs[kk][tx * 4];
            unsigned long long av[4] = {pack2(a4.x, a4.x), pack2(a4.y, a4.y),
                                        pack2(a4.z, a4.z), pack2(a4.w, a4.w)};
            #pragma unroll
            for (int i = 0; i < 4; i++) {
                fma_f32x2(acc2[i][0], av[i], bb.x, acc2[i][0]);
                fma_f32x2(acc2[i][1], av[i], bb.y, acc2[i][1]);
            }
        }
        __syncthreads();
    }
    int ty = tid >> 4, tx = tid & 15;
    #pragma unroll
    for (int i = 0; i < 4; i++) {
        int r = i0 + ty * 4 + i;
        float a0, a1, a2, a3;
        unpack2(a0, a1, acc2[i][0]);
        unpack2(a2, a3, acc2[i][1]);
        float accv[4] = {a0, a1, a2, a3};
        #pragma unroll
        for (int j = 0; j < 4; j++) {
            int c = j0 + tx * 4 + j;
            float v = accv[j];
            if (EPI == 1) v += bias[c];
            if (EPI == 2) {
                float cf = (float)cnt[r];
                v = (v + cf * pvb[c]) / (cf + 1.0f) + bias[c];
            }
            Cc[(size_t)r * CC + c] = v;
        }
    }
    if (EPI == 3) {
        if (blockIdx.x == 0 && tid < 64) aux[i0 + tid] = tacc;
    }
}

// ===== fused logits (tf32x3 mma.sync) + shuffle softmax(over G) + argmax + counts =====
// IDENTICAL to R13's measured-112us kernel.
__global__ void __launch_bounds__(128) k_attn(const float* __restrict__ key,
                                              float* __restrict__ soft,
                                              int* __restrict__ idxp,
                                              int* __restrict__ cntp) {
    __shared__ __align__(16) float sA[16][72];    // raw q2 (k-major)
    __shared__ __align__(16) float sB[16][136];   // raw key (k-major, swizzled cols)
    __shared__ float tsm[GG];

    int b = blockIdx.y;
    int n_base = blockIdx.x * 128;
    int tid = threadIdx.x, lane = tid & 31, warp = tid >> 5;
    if (tid < GG) tsm[tid] = g_t[b * GG + tid];

    const float* q2 = g_q2 + (size_t)b * GG * CC;
    const float* kp = key + ((size_t)b * NN + n_base) * CC;

    float acc[4][4][4];
    #pragma unroll
    for (int mt = 0; mt < 4; mt++)
        #pragma unroll
        for (int nt = 0; nt < 4; nt++)
            #pragma unroll
            for (int r = 0; r < 4; r++) acc[mt][nt][r] = 0.f;

    int kr = lane & 3, gr = lane >> 2;
    int wb = warp * 32;

    for (int k0 = 0; k0 < CC; k0 += 16) {
        {   // A (q2): 64g x 16k raw
            int g = tid >> 1, ks = (tid & 1) * 8;
            float4 v0 = *(const float4*)&q2[(size_t)g * CC + k0 + ks];
            float4 v1 = *(const float4*)&q2[(size_t)g * CC + k0 + ks + 4];
            float f[8] = {v0.x, v0.y, v0.z, v0.w, v1.x, v1.y, v1.z, v1.w};
            #pragma unroll
            for (int i = 0; i < 8; i++) sA[ks + i][g] = f[i];
        }
        #pragma unroll
        for (int p = 0; p < 4; p++) {  // B (key): 128n x 16k raw, swizzled cols
            int nn = (tid >> 2) + p * 32, kq = (tid & 3) * 4;
            float4 v = *(const float4*)&kp[(size_t)nn * CC + k0 + kq];
            float f[4] = {v.x, v.y, v.z, v.w};
            #pragma unroll
            for (int i = 0; i < 4; i++) {
                int r = kq + i;
                sB[r][nn ^ ((r & 12) << 1)] = f[i];
            }
        }
        __syncthreads();
        #pragma unroll
        for (int s = 0; s < 2; s++) {
            int k1 = s * 8 + kr, k2 = k1 + 4;
            int c1 = (k1 & 12) << 1, c2x = (k2 & 12) << 1;
            uint32_t bh[4][2], bl[4][2];
            #pragma unroll
            for (int nt = 0; nt < 4; nt++) {
                int nc = wb + nt * 8 + gr;
                float b0 = sB[k1][nc ^ c1];
                float b1 = sB[k2][nc ^ c2x];
                float h0 = maskhi(b0), h1 = maskhi(b1);
                bh[nt][0] = __float_as_uint(h0); bl[nt][0] = __float_as_uint(b0 - h0);
                bh[nt][1] = __float_as_uint(h1); bl[nt][1] = __float_as_uint(b1 - h1);
            }
            #pragma unroll
            for (int mt = 0; mt < 4; mt++) {
                int g0 = mt * 16 + gr;
                float a0 = sA[k1][g0], a1 = sA[k1][g0 + 8];
                float a2 = sA[k2][g0], a3 = sA[k2][g0 + 8];
                float h0 = maskhi(a0), h1 = maskhi(a1), h2 = maskhi(a2), h3 = maskhi(a3);
                uint32_t ah[4] = {__float_as_uint(h0), __float_as_uint(h1),
                                  __float_as_uint(h2), __float_as_uint(h3)};
                uint32_t al[4] = {__float_as_uint(a0 - h0), __float_as_uint(a1 - h1),
                                  __float_as_uint(a2 - h2), __float_as_uint(a3 - h3)};
                #pragma unroll
                for (int nt = 0; nt < 4; nt++) {
                    MMA_TF32(acc[mt][nt], ah, bh[nt]);
                    MMA_TF32(acc[mt][nt], ah, bl[nt]);
                    MMA_TF32(acc[mt][nt], al, bh[nt]);
                }
            }
        }
        __syncthreads();
    }

    // ---- shuffle-based softmax/argmax epilogue (no smem staging) ----
    float tv0[4], tv1[4];
    #pragma unroll
    for (int mt = 0; mt < 4; mt++) { tv0[mt] = tsm[16 * mt + gr]; tv1[mt] = tsm[16 * mt + 8 + gr]; }

    float* softb = soft + (size_t)b * GG * NN;
    #pragma unroll
    for (int nt = 0; nt < 4; nt++) {
        float e[2][8]; int am[2]; float inv[2];
        #pragma unroll
        for (int p = 0; p < 2; p++) {
            float l[8];
            #pragma unroll
            for (int mt = 0; mt < 4; mt++) {
                l[2 * mt]     = SCALE * (acc[mt][nt][p]     + tv0[mt]);
                l[2 * mt + 1] = SCALE * (acc[mt][nt][2 + p] + tv1[mt]);
            }
            float m = l[0]; int a = gr;
            #pragma unroll
            for (int i = 1; i < 8; i++) {
                int gi = 16 * (i >> 1) + 8 * (i & 1) + gr;
                if (l[i] > m) { m = l[i]; a = gi; }
            }
            #pragma unroll
            for (int o = 4; o <= 16; o <<= 1) {
                float mo = __shfl_xor_sync(0xFFFFFFFFu, m, o);
                int   ao = __shfl_xor_sync(0xFFFFFFFFu, a, o);
                if (mo > m || (mo == m && ao < a)) { m = mo; a = ao; }
            }
            float s = 0.f;
            #pragma unroll
            for (int i = 0; i < 8; i++) { e[p][i] = __expf(l[i] - m); s += e[p][i]; }
            #pragma unroll
            for (int o = 4; o <= 16; o <<= 1) s += __shfl_xor_sync(0xFFFFFFFFu, s, o);
            inv[p] = 1.0f / s; am[p] = a;
        }
        int cb = n_base + wb + nt * 8 + 2 * kr;
        #pragma unroll
        for (int mt = 0; mt < 4; mt++) {
            int g0 = 16 * mt + gr, g1 = g0 + 8;
            *(float2*)&softb[(size_t)g0 * NN + cb] =
                make_float2(e[0][2 * mt] * inv[0], e[1][2 * mt] * inv[1]);
            *(float2*)&softb[(size_t)g1 * NN + cb] =
                make_float2(e[0][2 * mt + 1] * inv[0], e[1][2 * mt + 1] * inv[1]);
        }
        if (gr == 0) {
            idxp[b * NN + cb]     = am[0];
            idxp[b * NN + cb + 1] = am[1];
            atomicAdd(&cntp[b * GG + am[0]], 1);
            atomicAdd(&cntp[b * GG + am[1]], 1);
        }
    }
}

// ---------------- segment sums of key rows by argmax group ----------------
// Pipelined: global key + idx loads for iter i+1 issue while iter i's serialized
// smem RMW chain drains (idx via GLOBAL loads -> no smem alias ordering).
// Each thread owns S column tid exclusively -> no block syncs needed.
__global__ void __launch_bounds__(128) k_seg(const float* __restrict__ key,
                                             const int* __restrict__ gidx) {
    __shared__ float S[GG][128];
    int ns = blockIdx.x, cb = blockIdx.y, b = blockIdx.z;
    int tid = threadIdx.x;
    int c0 = cb * 128, nb = ns * NR;
    #pragma unroll 4
    for (int i = tid; i < GG * 128; i += 128) ((float*)S)[i] = 0.f;   // col tid only
    const float* kp = key + ((size_t)(b * NN + nb)) * CC + c0 + tid;
    const int* ip = gidx + b * NN + nb;
    float x[8]; int six[8];
    #pragma unroll
    for (int i = 0; i < 8; i++) x[i] = kp[(size_t)i * CC];
    #pragma unroll
    for (int i = 0; i < 8; i++) six[i] = ip[i];
    for (int n = 0; n < NR - 8; n += 8) {
        float y[8]; int sy[8];
        #pragma unroll
        for (int i = 0; i < 8; i++) y[i] = kp[(size_t)(n + 8 + i) * CC];
        #pragma unroll
        for (int i = 0; i < 8; i++) sy[i] = ip[n + 8 + i];
        #pragma unroll
        for (int i = 0; i < 8; i++) S[six[i]][tid] += x[i];
        #pragma unroll
        for (int i = 0; i < 8; i++) { x[i] = y[i]; six[i] = sy[i]; }
    }
    #pragma unroll
    for (int i = 0; i < 8; i++) S[six[i]][tid] += x[i];
    float* dst = g_Sp + (size_t)ns * BB * GG * CC + (size_t)b * GG * CC + c0 + tid;
    #pragma unroll 4
    for (int g = 0; g < GG; g++) dst[(size_t)g * CC] = S[g][tid];
}

// ---------------- reduce NSEG partials -> g_S (deterministic ascending order) ----------
__global__ void __launch_bounds__(256) k_red() {
    size_t i = ((size_t)blockIdx.x * 256 + threadIdx.x) * 4;
    const size_t PS = (size_t)BB * GG * CC;
    float4 s = *(const float4*)&g_Sp[i];
    #pragma unroll
    for (int q = 1; q < NSEG; q++) {
        float4 v = *(const float4*)&g_Sp[(size_t)q * PS + i];
        s.x += v.x; s.y += v.y; s.z += v.z; s.w += v.w;
    }
    *(float4*)&g_S[i] = s;
}

// ---------------- launcher ----------------
extern "C" void kernel_launch(void* const* d_in, const int* in_sizes, int n_in,
                              void* d_out, int out_size) {
    const float* query = (const float*)d_in[0];
    const float* key   = (const float*)d_in[1];
    const float* q_w   = (const float*)d_in[2];
    const float* q_b   = (const float*)d_in[3];
    const float* k_w   = (const float*)d_in[4];
    const float* k_b   = (const float*)d_in[5];
    const float* v_w   = (const float*)d_in[6];
    const float* v_b   = (const float*)d_in[7];
    const float* p_w   = (const float*)d_in[8];
    const float* p_b   = (const float*)d_in[9];
    (void)n_in; (void)in_sizes;

    float* out  = (float*)d_out;
    float* soft = out + ((size_t)out_size - (size_t)BB * GG * NN);

    float *pqa, *pq2, *pMm, *ppvb, *pS, *pt;
    int *pidx, *pcnt;
    cudaGetSymbolAddress((void**)&pqa,  g_qa);
    cudaGetSymbolAddress((void**)&pq2,  g_q2);
    cudaGetSymbolAddress((void**)&pMm,  g_Mm);
    cudaGetSymbolAddress((void**)&ppvb, g_pvb);
    cudaGetSymbolAddress((void**)&pS,   g_S);
    cudaGetSymbolAddress((void**)&pt,   g_t);
    cudaGetSymbolAddress((void**)&pidx, g_idx);
    cudaGetSymbolAddress((void**)&pcnt, g_cnt);

    // 1. qa = query @ q_w.T + q_b
    k_gemm64<0, 1, 1><<<dim3(6, 32), 256>>>(query, q_w, pqa, q_b, nullptr, nullptr, nullptr);
    // 2. q2 = qa @ k_w ; t = qa . k_b (x==0) ; cnt = 0 (x==1)
    k_gemm64<0, 0, 3><<<dim3(6, 32), 256>>>(pqa, k_w, pq2, k_b, pcnt, nullptr, pt);
    // 3. fused logits(tf32x3 mma) + shuffle softmax + argmax + counts
    k_attn<<<dim3(NN / 128, BB), 128>>>(key, soft, pidx, pcnt);
    // 4. segment sums of key (pipelined)   <- ncu capture slot #4
    k_seg<<<dim3(NSEG, 3, BB), 128>>>(key, pidx);
    // 5. reduce partials -> g_S
    k_red<<<BB * GG * CC / 1024, 256>>>();
    // 6. Mm = p_w @ v_w ; pvb = p_w . v_b
    k_gemm64<0, 0, 3><<<dim3(6, 6), 256>>>(p_w, v_w, pMm, v_b, nullptr, nullptr, ppvb);
    // 7. out = (g_S @ Mm.T + cnt*pvb)/(cnt+1) + p_b
    k_gemm64<0, 1, 2><<<dim3(6, 32), 256>>>(pS, pMm, out, p_b, pcnt, ppvb, nullptr);
}